// round 6
// baseline (speedup 1.0000x reference)
#include <cuda_runtime.h>
#include <cuda_bf16.h>
#include <cstdint>

// Problem constants (fixed by the dataset)
#define BATCH 1024
#define DIM   512
#define MTOT  32768   // BATCH + R
#define RMEM  (MTOT - BATCH)

#define BM 128        // block tile rows (batch)
#define BN 128        // block tile cols (ref)
#define KC 32         // k-chunk
#define SW 20         // shared row stride in uint32 words (40 bf16 = 80B, conflict-free)

// ---------------- scratch (device globals; no runtime alloc) ----------------
__device__ __nv_bfloat16 g_B[(size_t)MTOT * DIM];   // bf16 copy of [batch ++ mem]
__device__ float g_sqb[MTOT];                        // squared norms (fp32, exact)
__device__ int   g_lbl[MTOT];                        // merged labels as int32
__device__ float g_ps[BATCH], g_pc[BATCH], g_ns[BATCH], g_nc[BATCH];
__device__ int   g_lab64;                            // 1 if labels are int64

// ---------------- kernel 0: detect int64 vs int32 labels ----------------
__global__ void detect_kernel(const int* lab, const int* lmem) {
    int hi = 0;
    if (threadIdx.x < 16) hi = lab[threadIdx.x * 2 + 1];
    else                  hi = lmem[(threadIdx.x - 16) * 2 + 1];
    unsigned any = __ballot_sync(0xFFFFFFFFu, hi != 0);
    if (threadIdx.x == 0) g_lab64 = (any == 0) ? 1 : 0;
}

// ---------------- kernel 1: prep (convert + norms + labels + zero accum) ----------------
__global__ __launch_bounds__(128) void prep_kernel(
    const float* __restrict__ emb, const int* __restrict__ lab,
    const float* __restrict__ mem, const int* __restrict__ lmem)
{
    int r = blockIdx.x;
    int tid = threadIdx.x;                 // 128 threads, 4 floats each
    const float* src = (r < BATCH) ? (emb + (size_t)r * DIM)
                                   : (mem + (size_t)(r - BATCH) * DIM);
    float4 v = reinterpret_cast<const float4*>(src)[tid];
    float s = v.x * v.x + v.y * v.y + v.z * v.z + v.w * v.w;

    __nv_bfloat162* dst = reinterpret_cast<__nv_bfloat162*>(g_B + (size_t)r * DIM);
    dst[tid * 2 + 0] = __floats2bfloat162_rn(v.x, v.y);
    dst[tid * 2 + 1] = __floats2bfloat162_rn(v.z, v.w);

    #pragma unroll
    for (int o = 16; o; o >>= 1) s += __shfl_xor_sync(0xFFFFFFFFu, s, o);
    __shared__ float ws[4];
    if ((tid & 31) == 0) ws[tid >> 5] = s;
    __syncthreads();
    if (tid == 0) {
        g_sqb[r] = ws[0] + ws[1] + ws[2] + ws[3];
        int lv;
        if (r < BATCH) lv = g_lab64 ? lab[2 * r]            : lab[r];
        else           lv = g_lab64 ? lmem[2 * (r - BATCH)] : lmem[r - BATCH];
        g_lbl[r] = lv;
        if (r < BATCH) { g_ps[r] = 0.f; g_pc[r] = 0.f; g_ns[r] = 0.f; g_nc[r] = 0.f; }
    }
}

// ---------------- kernel 2: main GEMM + epilogue ----------------
__device__ __forceinline__ void mma16816(float c[4], const uint32_t a[4], const uint32_t b[2]) {
    asm volatile(
        "mma.sync.aligned.m16n8k16.row.col.f32.bf16.bf16.f32 "
        "{%0,%1,%2,%3}, {%4,%5,%6,%7}, {%8,%9}, {%0,%1,%2,%3};\n"
        : "+f"(c[0]), "+f"(c[1]), "+f"(c[2]), "+f"(c[3])
        : "r"(a[0]), "r"(a[1]), "r"(a[2]), "r"(a[3]), "r"(b[0]), "r"(b[1]));
}

__global__ __launch_bounds__(256, 2) void main_kernel()
{
    __shared__ uint32_t As[2][BM * SW];
    __shared__ uint32_t Bs[2][BN * SW];
    __shared__ float s_ps[BM], s_pc[BM], s_ns[BM], s_nc[BM];

    const int tid  = threadIdx.x;
    const int lane = tid & 31;
    const int warp = tid >> 5;
    const int g  = lane >> 2;      // group id 0..7
    const int tg = lane & 3;       // thread-in-group 0..3
    const int wr = warp >> 2;      // warp row 0..1 (64 rows each)
    const int wc = warp & 3;       // warp col 0..3 (32 cols each)
    const int rowBase = blockIdx.y * BM;
    const int colBase = blockIdx.x * BN;

    if (tid < BM) { s_ps[tid] = 0.f; s_pc[tid] = 0.f; s_ns[tid] = 0.f; s_nc[tid] = 0.f; }

    float acc[4][4][4];
    #pragma unroll
    for (int a = 0; a < 4; a++)
        #pragma unroll
        for (int b = 0; b < 4; b++)
            #pragma unroll
            for (int c = 0; c < 4; c++) acc[a][b][c] = 0.f;

    // global load geometry: 256 threads, each loads 16 bf16 of A-tile and B-tile per chunk
    const int lr  = tid >> 1;                  // 0..127 local row
    const int lkw = (tid & 1) * 8;             // shared word offset (0 or 8 -> k 0..15 / 16..31)
    const uint4* gA = reinterpret_cast<const uint4*>(g_B + ((size_t)(rowBase + lr) << 9)) + (tid & 1) * 2;
    const uint4* gR = reinterpret_cast<const uint4*>(g_B + ((size_t)(colBase + lr) << 9)) + (tid & 1) * 2;

    // prologue: chunk 0
    uint4 ra0 = gA[0], ra1 = gA[1];
    uint4 rb0 = gR[0], rb1 = gR[1];
    {
        uint4* p = reinterpret_cast<uint4*>(&As[0][lr * SW + lkw]); p[0] = ra0; p[1] = ra1;
        uint4* q = reinterpret_cast<uint4*>(&Bs[0][lr * SW + lkw]); q[0] = rb0; q[1] = rb1;
    }
    __syncthreads();

    const int NCHUNK = DIM / KC;   // 16
    for (int c = 0; c < NCHUNK; ++c) {
        const int cur = c & 1;
        const bool more = (c + 1) < NCHUNK;
        if (more) {
            const uint4* pa = gA + (size_t)(c + 1) * 4;
            const uint4* pb = gR + (size_t)(c + 1) * 4;
            ra0 = pa[0]; ra1 = pa[1]; rb0 = pb[0]; rb1 = pb[1];
        }
        // compute on buffer cur: two k16 steps
        const uint32_t* Ash = As[cur];
        const uint32_t* Bsh = Bs[cur];
        #pragma unroll
        for (int ks = 0; ks < 2; ++ks) {
            const int kw = ks * 8;
            uint32_t afr[4][4], bfr[4][2];
            #pragma unroll
            for (int mt = 0; mt < 4; ++mt) {
                int r0 = wr * 64 + mt * 16 + g;
                afr[mt][0] = Ash[r0 * SW + kw + tg];
                afr[mt][1] = Ash[(r0 + 8) * SW + kw + tg];
                afr[mt][2] = Ash[r0 * SW + kw + tg + 4];
                afr[mt][3] = Ash[(r0 + 8) * SW + kw + tg + 4];
            }
            #pragma unroll
            for (int nt = 0; nt < 4; ++nt) {
                int nc0 = wc * 32 + nt * 8 + g;
                bfr[nt][0] = Bsh[nc0 * SW + kw + tg];
                bfr[nt][1] = Bsh[nc0 * SW + kw + tg + 4];
            }
            #pragma unroll
            for (int mt = 0; mt < 4; ++mt)
                #pragma unroll
                for (int nt = 0; nt < 4; ++nt)
                    mma16816(acc[mt][nt], afr[mt], bfr[nt]);
        }
        __syncthreads();
        if (more) {
            uint4* p = reinterpret_cast<uint4*>(&As[cur ^ 1][lr * SW + lkw]); p[0] = ra0; p[1] = ra1;
            uint4* q = reinterpret_cast<uint4*>(&Bs[cur ^ 1][lr * SW + lkw]); q[0] = rb0; q[1] = rb1;
            __syncthreads();
        }
    }

    // -------- epilogue --------
    // j-side values (same 8 columns for every row this thread touches)
    float sbv[8]; int lbv[8];
    #pragma unroll
    for (int nt = 0; nt < 4; ++nt)
        #pragma unroll
        for (int cc = 0; cc < 2; ++cc) {
            int gj = colBase + wc * 32 + nt * 8 + tg * 2 + cc;
            sbv[nt * 2 + cc] = g_sqb[gj];
            lbv[nt * 2 + cc] = g_lbl[gj];
        }

    #pragma unroll
    for (int mt = 0; mt < 4; ++mt) {
        #pragma unroll
        for (int rh = 0; rh < 2; ++rh) {
            int li = wr * 64 + mt * 16 + rh * 8 + g;
            int gi = rowBase + li;
            float sa = g_sqb[gi];
            int   la = g_lbl[gi];
            float ps = 0.f, pc = 0.f, ng = 0.f, ngc = 0.f;
            #pragma unroll
            for (int nt = 0; nt < 4; ++nt)
                #pragma unroll
                for (int cc = 0; cc < 2; ++cc) {
                    int idx = nt * 2 + cc;
                    int gj = colBase + wc * 32 + nt * 8 + tg * 2 + cc;
                    float dot = acc[mt][nt][rh * 2 + cc];
                    float dd = fmaxf(sa + sbv[idx] - 2.0f * dot, 0.0f);
                    bool same  = (la == lbv[idx]);
                    bool nself = (gj != gi);
                    if (same && nself && dd > 0.0f) { ps += dd; pc += 1.0f; }
                    float an = 1.0f - dd;
                    if (!same && nself && an > 0.0f) { ng += an; ngc += 1.0f; }
                }
            // reduce across the 4 lanes sharing this row (tg = 0..3)
            #pragma unroll
            for (int o = 1; o < 4; o <<= 1) {
                ps  += __shfl_xor_sync(0xFFFFFFFFu, ps,  o);
                pc  += __shfl_xor_sync(0xFFFFFFFFu, pc,  o);
                ng  += __shfl_xor_sync(0xFFFFFFFFu, ng,  o);
                ngc += __shfl_xor_sync(0xFFFFFFFFu, ngc, o);
            }
            if (tg == 0) {
                atomicAdd(&s_ps[li], ps);
                atomicAdd(&s_pc[li], pc);
                atomicAdd(&s_ns[li], ng);
                atomicAdd(&s_nc[li], ngc);
            }
        }
    }
    __syncthreads();
    if (tid < BM) {
        atomicAdd(&g_ps[rowBase + tid], s_ps[tid]);
        atomicAdd(&g_pc[rowBase + tid], s_pc[tid]);
        atomicAdd(&g_ns[rowBase + tid], s_ns[tid]);
        atomicAdd(&g_nc[rowBase + tid], s_nc[tid]);
    }
}

// ---------------- kernel 3: final scalar reduce ----------------
__global__ __launch_bounds__(1024) void final_kernel(float* out)
{
    int tid = threadIdx.x;
    float v = g_ps[tid] / (g_pc[tid] + 1e-6f) + g_ns[tid] / (g_nc[tid] + 1e-6f);
    #pragma unroll
    for (int o = 16; o; o >>= 1) v += __shfl_xor_sync(0xFFFFFFFFu, v, o);
    __shared__ float red[32];
    if ((tid & 31) == 0) red[tid >> 5] = v;
    __syncthreads();
    if (tid < 32) {
        float t = red[tid];
        #pragma unroll
        for (int o = 16; o; o >>= 1) t += __shfl_xor_sync(0xFFFFFFFFu, t, o);
        if (tid == 0) out[0] = t * (1.0f / (float)BATCH);
    }
}

// ---------------- launch ----------------
extern "C" void kernel_launch(void* const* d_in, const int* in_sizes, int n_in,
                              void* d_out, int out_size)
{
    const float* emb  = (const float*)d_in[0];
    const int*   lab  = (const int*)d_in[1];   // int32 view; int64 handled via g_lab64
    const float* mem  = (const float*)d_in[2];
    const int*   lmem = (const int*)d_in[3];
    float* out = (float*)d_out;

    detect_kernel<<<1, 32>>>(lab, lmem);
    prep_kernel<<<MTOT, 128>>>(emb, lab, mem, lmem);
    main_kernel<<<dim3(MTOT / BN, BATCH / BM), 256>>>();
    final_kernel<<<1, 1024>>>(out);
}

// round 11
// speedup vs baseline: 1.0720x; 1.0720x over previous
#include <cuda_runtime.h>
#include <cuda_bf16.h>
#include <cstdint>

// Problem constants (fixed by the dataset)
#define BATCH 1024
#define DIM   512
#define MTOT  32768

#define BM 128        // block tile rows (batch)
#define BN 128        // block tile cols (ref)
#define KC 32         // k elements per pipeline stage
#define NCHUNK 16     // 512 / 32
#define SW 20         // shared row stride in words (80B: 16B-aligned, LDSM conflict-free)
#define STAGES 3
#define STAGE_WORDS (BM * SW)            // per operand per stage (2560 words = 10240B)
#define STAGE_BYTES (2 * STAGE_WORDS * 4) // A+B per stage = 20480B
#define DSMEM_BYTES (STAGES * STAGE_BYTES) // 61440

// ---------------- scratch (device globals; no runtime alloc) ----------------
__device__ __nv_bfloat16 g_B[(size_t)MTOT * DIM];   // bf16 copy of [batch ++ mem]
__device__ float g_sqb[MTOT];
__device__ int   g_lbl[MTOT];
__device__ float g_ps[BATCH], g_pc[BATCH], g_ns[BATCH], g_nc[BATCH];
__device__ int   g_lab64;
__device__ unsigned int g_done;   // zero-init; last CTA resets each run

// ---------------- helpers ----------------
static __device__ __forceinline__ uint32_t smem_u32(const void* p) {
    uint32_t a;
    asm("{ .reg .u64 t; cvta.to.shared.u64 t, %1; cvt.u32.u64 %0, t; }" : "=r"(a) : "l"(p));
    return a;
}
static __device__ __forceinline__ void cp16(uint32_t dst, const void* src) {
    asm volatile("cp.async.cg.shared.global [%0], [%1], 16;" :: "r"(dst), "l"(src));
}
static __device__ __forceinline__ void cp_commit() {
    asm volatile("cp.async.commit_group;");
}
static __device__ __forceinline__ void cp_wait2() {
    asm volatile("cp.async.wait_group 2;");
}
static __device__ __forceinline__ void ldsm_x4(uint32_t& d0, uint32_t& d1, uint32_t& d2, uint32_t& d3, uint32_t addr) {
    asm volatile("ldmatrix.sync.aligned.m8n8.x4.shared.b16 {%0,%1,%2,%3}, [%4];"
                 : "=r"(d0), "=r"(d1), "=r"(d2), "=r"(d3) : "r"(addr));
}
static __device__ __forceinline__ void mma16816(float c[4], const uint32_t a[4], const uint32_t b[2]) {
    asm volatile(
        "mma.sync.aligned.m16n8k16.row.col.f32.bf16.bf16.f32 "
        "{%0,%1,%2,%3}, {%4,%5,%6,%7}, {%8,%9}, {%0,%1,%2,%3};\n"
        : "+f"(c[0]), "+f"(c[1]), "+f"(c[2]), "+f"(c[3])
        : "r"(a[0]), "r"(a[1]), "r"(a[2]), "r"(a[3]), "r"(b[0]), "r"(b[1]));
}

// ---------------- kernel 0: detect int64 vs int32 labels ----------------
__global__ void detect_kernel(const int* lab, const int* lmem) {
    int hi = 0;
    if (threadIdx.x < 16) hi = lab[threadIdx.x * 2 + 1];
    else                  hi = lmem[(threadIdx.x - 16) * 2 + 1];
    unsigned any = __ballot_sync(0xFFFFFFFFu, hi != 0);
    if (threadIdx.x == 0) g_lab64 = (any == 0) ? 1 : 0;
}

// ---------------- kernel 1: prep (convert + norms + labels + zero accum) ----------------
__global__ __launch_bounds__(128) void prep_kernel(
    const float* __restrict__ emb, const int* __restrict__ lab,
    const float* __restrict__ mem, const int* __restrict__ lmem)
{
    int r = blockIdx.x;
    int tid = threadIdx.x;                 // 128 threads, 4 floats each
    const float* src = (r < BATCH) ? (emb + (size_t)r * DIM)
                                   : (mem + (size_t)(r - BATCH) * DIM);
    float4 v = reinterpret_cast<const float4*>(src)[tid];
    float s = v.x * v.x + v.y * v.y + v.z * v.z + v.w * v.w;

    __nv_bfloat162* dst = reinterpret_cast<__nv_bfloat162*>(g_B + (size_t)r * DIM);
    dst[tid * 2 + 0] = __floats2bfloat162_rn(v.x, v.y);
    dst[tid * 2 + 1] = __floats2bfloat162_rn(v.z, v.w);

    #pragma unroll
    for (int o = 16; o; o >>= 1) s += __shfl_xor_sync(0xFFFFFFFFu, s, o);
    __shared__ float ws[4];
    if ((tid & 31) == 0) ws[tid >> 5] = s;
    __syncthreads();
    if (tid == 0) {
        g_sqb[r] = ws[0] + ws[1] + ws[2] + ws[3];
        int lv;
        if (r < BATCH) lv = g_lab64 ? lab[2 * r]            : lab[r];
        else           lv = g_lab64 ? lmem[2 * (r - BATCH)] : lmem[r - BATCH];
        g_lbl[r] = lv;
        if (r < BATCH) { g_ps[r] = 0.f; g_pc[r] = 0.f; g_ns[r] = 0.f; g_nc[r] = 0.f; }
    }
}

// ---------------- kernel 2: GEMM (ldmatrix + cp.async pipeline) + epilogue + last-CTA reduce ----------------
__global__ __launch_bounds__(256, 2) void main_kernel(float* __restrict__ out)
{
    extern __shared__ uint32_t sm[];
    __shared__ float s_ps[BM], s_pc[BM], s_ns[BM], s_nc[BM];
    __shared__ int   s_islast;
    __shared__ float s_red[8];

    const int tid  = threadIdx.x;
    const int lane = tid & 31;
    const int warp = tid >> 5;
    const int g  = lane >> 2;      // group id 0..7
    const int tg = lane & 3;       // thread-in-group 0..3
    const int wr = warp >> 2;      // warp row 0..1 (64 rows each)
    const int wc = warp & 3;       // warp col 0..3 (32 cols each)
    const int rowBase = blockIdx.y * BM;
    const int colBase = blockIdx.x * BN;

    const uint32_t sbase = smem_u32(sm);

    if (tid < BM) { s_ps[tid] = 0.f; s_pc[tid] = 0.f; s_ns[tid] = 0.f; s_nc[tid] = 0.f; }

    float acc[4][4][4];
    #pragma unroll
    for (int a = 0; a < 4; a++)
        #pragma unroll
        for (int b = 0; b < 4; b++)
            #pragma unroll
            for (int c = 0; c < 4; c++) acc[a][b][c] = 0.f;

    // cp.async geometry: per stage each thread fills 32B of one A row and one B row
    const int lr = tid >> 1;                      // local row 0..127
    const int qb = (tid & 1) * 32;                // byte offset within the 64B row-chunk
    const uint32_t dwOff = ((lr * SW) << 2) + ((tid & 1) * 8 << 2);   // dst byte offset in buffer
    const char* srcArow = reinterpret_cast<const char*>(g_B) + (((size_t)(rowBase + lr)) << 10) + qb;
    const char* srcBrow = reinterpret_cast<const char*>(g_B) + (((size_t)(colBase + lr)) << 10) + qb;

    // prologue: stages 0..2
    #pragma unroll
    for (int s = 0; s < STAGES; ++s) {
        uint32_t aA = sbase + s * STAGE_BYTES + dwOff;
        uint32_t aB = aA + STAGE_WORDS * 4;
        const char* sA = srcArow + s * 64;
        const char* sB = srcBrow + s * 64;
        cp16(aA, sA); cp16(aA + 16, sA + 16);
        cp16(aB, sB); cp16(aB + 16, sB + 16);
        cp_commit();
    }

    // ldmatrix per-lane addressing (same formula for A and B)
    const int frow  = lane & 15;                  // row within 16-row group
    const int fkoff = (lane >> 4) * 4;            // word offset selecting k-half

    for (int c = 0; c < NCHUNK; ++c) {
        cp_wait2();                               // stage c complete
        __syncthreads();
        const int buf = c % STAGES;
        const uint32_t Aoff = sbase + buf * STAGE_BYTES;
        const uint32_t Boff = Aoff + STAGE_WORDS * 4;

        #pragma unroll
        for (int ks = 0; ks < 2; ++ks) {
            const int kw = ks * 8;
            uint32_t afr[4][4], bfr[4][2];
            #pragma unroll
            for (int mt = 0; mt < 4; ++mt) {
                int row = wr * 64 + mt * 16 + frow;
                uint32_t addr = Aoff + ((row * SW + kw + fkoff) << 2);
                ldsm_x4(afr[mt][0], afr[mt][1], afr[mt][2], afr[mt][3], addr);
            }
            #pragma unroll
            for (int h = 0; h < 2; ++h) {
                int nrow = wc * 32 + h * 16 + frow;
                uint32_t addr = Boff + ((nrow * SW + kw + fkoff) << 2);
                uint32_t t0, t1, t2, t3;
                ldsm_x4(t0, t1, t2, t3, addr);
                bfr[h * 2 + 0][0] = t0; bfr[h * 2 + 0][1] = t2;
                bfr[h * 2 + 1][0] = t1; bfr[h * 2 + 1][1] = t3;
            }
            #pragma unroll
            for (int mt = 0; mt < 4; ++mt)
                #pragma unroll
                for (int nt = 0; nt < 4; ++nt)
                    mma16816(acc[mt][nt], afr[mt], bfr[nt]);
        }
        __syncthreads();                          // all warps done reading buf
        if (c + STAGES < NCHUNK) {                // refill buf with stage c+3
            uint32_t aA = sbase + buf * STAGE_BYTES + dwOff;
            uint32_t aB = aA + STAGE_WORDS * 4;
            const char* sA = srcArow + (size_t)(c + STAGES) * 64;
            const char* sB = srcBrow + (size_t)(c + STAGES) * 64;
            cp16(aA, sA); cp16(aA + 16, sA + 16);
            cp16(aB, sB); cp16(aB + 16, sB + 16);
        }
        cp_commit();                              // empty-group commit in the tail keeps accounting uniform
    }

    // -------- epilogue --------
    float sbv[8]; int lbv[8];
    #pragma unroll
    for (int nt = 0; nt < 4; ++nt)
        #pragma unroll
        for (int cc = 0; cc < 2; ++cc) {
            int gj = colBase + wc * 32 + nt * 8 + tg * 2 + cc;
            sbv[nt * 2 + cc] = g_sqb[gj];
            lbv[nt * 2 + cc] = g_lbl[gj];
        }

    #pragma unroll
    for (int mt = 0; mt < 4; ++mt) {
        #pragma unroll
        for (int rh = 0; rh < 2; ++rh) {
            int li = wr * 64 + mt * 16 + rh * 8 + g;
            int gi = rowBase + li;
            float sa = g_sqb[gi];
            int   la = g_lbl[gi];
            float ps = 0.f, pc = 0.f, ng = 0.f, ngc = 0.f;
            #pragma unroll
            for (int nt = 0; nt < 4; ++nt)
                #pragma unroll
                for (int cc = 0; cc < 2; ++cc) {
                    int idx = nt * 2 + cc;
                    int gj = colBase + wc * 32 + nt * 8 + tg * 2 + cc;
                    float dot = acc[mt][nt][rh * 2 + cc];
                    float dd = fmaxf(sa + sbv[idx] - 2.0f * dot, 0.0f);
                    bool same  = (la == lbv[idx]);
                    bool nself = (gj != gi);
                    if (same && nself && dd > 0.0f) { ps += dd; pc += 1.0f; }
                    float an = 1.0f - dd;
                    if (!same && nself && an > 0.0f) { ng += an; ngc += 1.0f; }
                }
            #pragma unroll
            for (int o = 1; o < 4; o <<= 1) {
                ps  += __shfl_xor_sync(0xFFFFFFFFu, ps,  o);
                pc  += __shfl_xor_sync(0xFFFFFFFFu, pc,  o);
                ng  += __shfl_xor_sync(0xFFFFFFFFu, ng,  o);
                ngc += __shfl_xor_sync(0xFFFFFFFFu, ngc, o);
            }
            if (tg == 0) {
                atomicAdd(&s_ps[li], ps);
                atomicAdd(&s_pc[li], pc);
                atomicAdd(&s_ns[li], ng);
                atomicAdd(&s_nc[li], ngc);
            }
        }
    }
    __syncthreads();
    if (tid < BM) {
        atomicAdd(&g_ps[rowBase + tid], s_ps[tid]);
        atomicAdd(&g_pc[rowBase + tid], s_pc[tid]);
        atomicAdd(&g_ns[rowBase + tid], s_ns[tid]);
        atomicAdd(&g_nc[rowBase + tid], s_nc[tid]);
    }

    // -------- last-CTA final reduction (replaces separate final kernel) --------
    __threadfence();
    __syncthreads();
    if (tid == 0) {
        unsigned o = atomicAdd(&g_done, 1u);
        s_islast = (o == (unsigned)(gridDim.x * gridDim.y) - 1u) ? 1 : 0;
    }
    __syncthreads();
    if (s_islast) {
        __threadfence();
        float v = 0.f;
        for (int i = tid; i < BATCH; i += 256)
            v += g_ps[i] / (g_pc[i] + 1e-6f) + g_ns[i] / (g_nc[i] + 1e-6f);
        #pragma unroll
        for (int o = 16; o; o >>= 1) v += __shfl_xor_sync(0xFFFFFFFFu, v, o);
        if (lane == 0) s_red[warp] = v;
        __syncthreads();
        if (tid == 0) {
            float t = 0.f;
            #pragma unroll
            for (int w = 0; w < 8; w++) t += s_red[w];
            out[0] = t * (1.0f / (float)BATCH);
            g_done = 0;   // reset for next graph replay
        }
    }
}

// ---------------- launch ----------------
extern "C" void kernel_launch(void* const* d_in, const int* in_sizes, int n_in,
                              void* d_out, int out_size)
{
    const float* emb  = (const float*)d_in[0];
    const int*   lab  = (const int*)d_in[1];   // int32 view; int64 handled via g_lab64
    const float* mem  = (const float*)d_in[2];
    const int*   lmem = (const int*)d_in[3];
    float* out = (float*)d_out;

    cudaFuncSetAttribute(main_kernel, cudaFuncAttributeMaxDynamicSharedMemorySize, DSMEM_BYTES);

    detect_kernel<<<1, 32>>>(lab, lmem);
    prep_kernel<<<MTOT, 128>>>(emb, lab, mem, lmem);
    main_kernel<<<dim3(MTOT / BN, BATCH / BM), 256, DSMEM_BYTES>>>(out);
}